// round 11
// baseline (speedup 1.0000x reference)
#include <cuda_runtime.h>
#include <cuda_bf16.h>
#include <cstdint>

#define N_NODES 100000
#define N_EDGES 600000
#define F_IN 128
#define F_OUT 64
#define TM 128
#define AP 136                 // smem pitch in bf16 (272B rows: 16B-aligned, conflict-free)

// Scratch (no allocation allowed in kernel_launch)
__device__ float s_xp[(size_t)N_NODES * F_OUT];
__device__ float s_deg[N_NODES];   // zero-init; gemm epilogue re-zeroes after use
__device__ float s_dis[N_NODES];

// dynamic smem byte offsets for k_gemm
#define SM_AHI 0                          // 128*136*2 = 34816
#define SM_ALO 34816
#define SM_BHI 69632                      // 64*136*2 = 17408
#define SM_BLO 87040
#define SM_TOTAL 104448

__device__ __forceinline__ uint32_t smem_u32(const void* p) {
    uint32_t a;
    asm("{ .reg .u64 t; cvta.to.shared.u64 t, %1; cvt.u32.u64 %0, t; }" : "=r"(a) : "l"(p));
    return a;
}

#define LDSM_X4(r, addr) \
    asm volatile("ldmatrix.sync.aligned.m8n8.x4.shared.b16 {%0,%1,%2,%3}, [%4];" \
        : "=r"((r)[0]), "=r"((r)[1]), "=r"((r)[2]), "=r"((r)[3]) : "r"(addr))
#define LDSM_X2(r, addr) \
    asm volatile("ldmatrix.sync.aligned.m8n8.x2.shared.b16 {%0,%1}, [%2];" \
        : "=r"((r)[0]), "=r"((r)[1]) : "r"(addr))
#define MMA_BF16(c, a, b) \
    asm volatile("mma.sync.aligned.m16n8k16.row.col.f32.bf16.bf16.f32 " \
        "{%0,%1,%2,%3}, {%4,%5,%6,%7}, {%8,%9}, {%0,%1,%2,%3};" \
        : "+f"((c)[0]), "+f"((c)[1]), "+f"((c)[2]), "+f"((c)[3]) \
        : "r"((a)[0]), "r"((a)[1]), "r"((a)[2]), "r"((a)[3]), "r"((b)[0]), "r"((b)[1]))

// ---------------------------------------------------------------------------
__global__ void k_deg_acc(const int* __restrict__ ei,
                          const float* __restrict__ ew) {
    int e = blockIdx.x * blockDim.x + threadIdx.x;
    if (e < N_EDGES) {
        int col = ei[N_EDGES + e];
        float w = 1.f / (1.f + __expf(-ew[e]));
        atomicAdd(&s_deg[col], w);
    }
}

// ---------------------------------------------------------------------------
// Fused: sigma power-iter + tensor GEMM (mma.sync bf16 3-term split) +
// epilogue (out = xp/(deg+1) + bias, stash xp, s_dis = sqrt(1/(deg+1)),
// reset s_deg for next replay).
// Block: 128 rows x 64 cols, 256 threads (8 warps: 4 m-groups x 2 n-groups).
// ---------------------------------------------------------------------------
__global__ __launch_bounds__(256) void k_gemm(const float* __restrict__ x,
                                              const float* __restrict__ W,
                                              const float* __restrict__ bias,
                                              const float* __restrict__ u,
                                              float* __restrict__ out) {
    extern __shared__ char smem[];
    __shared__ float sv[F_OUT];
    __shared__ float sred[256];
    __shared__ float n1s, s_is;

    uint32_t sb = smem_u32(smem);
    int tid = threadIdx.x;
    int wid = tid >> 5;
    int lane = tid & 31;
    int mwid = wid & 3;       // m-group: 32 rows
    int nwid = wid >> 2;      // n-group: 32 cols
    int r0 = blockIdx.x * TM;

    // ---- inline sigma: v = W^T u ; inv_sigma = ||v|| / ||W v||
    if (tid < F_OUT) {
        float s = 0.f;
        for (int i = 0; i < F_IN; i++) s += W[i * F_OUT + tid] * u[i];
        sv[tid] = s;
    }
    __syncthreads();
    sred[tid] = (tid < F_OUT) ? sv[tid] * sv[tid] : 0.f;
    __syncthreads();
    for (int s = 128; s > 0; s >>= 1) {
        if (tid < s) sred[tid] += sred[tid + s];
        __syncthreads();
    }
    if (tid == 0) n1s = sqrtf(sred[0]);
    __syncthreads();
    {
        float g = 0.f;
        if (tid < F_IN) {
            for (int j = 0; j < F_OUT; j++) g += W[tid * F_OUT + j] * sv[j];
        }
        sred[tid] = (tid < F_IN) ? g * g : 0.f;
    }
    __syncthreads();
    for (int s = 128; s > 0; s >>= 1) {
        if (tid < s) sred[tid] += sred[tid + s];
        __syncthreads();
    }
    if (tid == 0) s_is = n1s / sqrtf(sred[0]);
    __syncthreads();
    float inv_sigma = s_is;

    // ---- A: x[r0:r0+128, :] -> bf16 hi/lo into padded smem [128][AP]
    __nv_bfloat16* Ahi = (__nv_bfloat16*)(smem + SM_AHI);
    __nv_bfloat16* Alo = (__nv_bfloat16*)(smem + SM_ALO);
    #pragma unroll 4
    for (int it = 0; it < 16; it++) {
        int idx = it * 256 + tid;        // float4 slot, 4096 total
        int row = idx >> 5;
        int k4 = (idx & 31) * 4;
        int grow = r0 + row;
        float4 v = make_float4(0.f, 0.f, 0.f, 0.f);
        if (grow < N_NODES) v = *(const float4*)&x[(size_t)grow * F_IN + k4];

        float fv[4] = {v.x, v.y, v.z, v.w};
        __nv_bfloat16 h[4], l[4];
        #pragma unroll
        for (int j = 0; j < 4; j++) {
            h[j] = __float2bfloat16_rn(fv[j]);
            l[j] = __float2bfloat16_rn(fv[j] - __bfloat162float(h[j]));
        }
        int base = row * AP + k4;
        *(__nv_bfloat162*)&Ahi[base]     = __nv_bfloat162(h[0], h[1]);
        *(__nv_bfloat162*)&Ahi[base + 2] = __nv_bfloat162(h[2], h[3]);
        *(__nv_bfloat162*)&Alo[base]     = __nv_bfloat162(l[0], l[1]);
        *(__nv_bfloat162*)&Alo[base + 2] = __nv_bfloat162(l[2], l[3]);
    }

    // ---- B: B[n][k] = bf16(W[k][n] * inv_sigma); thread: k=tid>>1, half n range
    __nv_bfloat16* Bhi = (__nv_bfloat16*)(smem + SM_BHI);
    __nv_bfloat16* Blo = (__nv_bfloat16*)(smem + SM_BLO);
    {
        int k = tid >> 1;
        int n4base = (tid & 1) * 8;
        const float4* wr = (const float4*)(W + (size_t)k * F_OUT);
        #pragma unroll
        for (int n4i = 0; n4i < 8; n4i++) {
            int n4 = n4base + n4i;
            float4 wv = wr[n4];
            float vv[4] = {wv.x * inv_sigma, wv.y * inv_sigma,
                           wv.z * inv_sigma, wv.w * inv_sigma};
            #pragma unroll
            for (int j = 0; j < 4; j++) {
                int n = n4 * 4 + j;
                __nv_bfloat16 h = __float2bfloat16_rn(vv[j]);
                __nv_bfloat16 l = __float2bfloat16_rn(vv[j] - __bfloat162float(h));
                Bhi[n * AP + k] = h;
                Blo[n * AP + k] = l;
            }
        }
    }
    __syncthreads();

    // ---- fragment mainloop: each warp 32 rows (2 m16) x 32 cols (4 n8)
    float acc[2][4][4];
    #pragma unroll
    for (int mt = 0; mt < 2; mt++)
        #pragma unroll
        for (int nt = 0; nt < 4; nt++)
            #pragma unroll
            for (int j = 0; j < 4; j++) acc[mt][nt][j] = 0.f;

    int lm = lane & 15;
    int lk = (lane >> 4) * 8;
    int bn = lane & 7;
    int bk = ((lane >> 3) & 1) * 8;

    uint32_t aH0 = sb + SM_AHI + (uint32_t)(mwid * 32 + lm) * AP * 2;
    uint32_t aH1 = aH0 + 16u * AP * 2;
    uint32_t aL0 = sb + SM_ALO + (uint32_t)(mwid * 32 + lm) * AP * 2;
    uint32_t aL1 = aL0 + 16u * AP * 2;
    uint32_t bH  = sb + SM_BHI + (uint32_t)(nwid * 32 + bn) * AP * 2;
    uint32_t bL  = sb + SM_BLO + (uint32_t)(nwid * 32 + bn) * AP * 2;

    #pragma unroll
    for (int ks = 0; ks < 8; ks++) {
        int kb = ks * 16;
        uint32_t aoff = (uint32_t)(kb + lk) * 2;
        uint32_t boff = (uint32_t)(kb + bk) * 2;

        uint32_t ah0[4], ah1[4], al0[4], al1[4];
        LDSM_X4(ah0, aH0 + aoff);
        LDSM_X4(ah1, aH1 + aoff);
        LDSM_X4(al0, aL0 + aoff);
        LDSM_X4(al1, aL1 + aoff);

        #pragma unroll
        for (int nt = 0; nt < 4; nt++) {
            uint32_t bh[2], bl[2];
            uint32_t nstep = (uint32_t)(nt * 8) * AP * 2;
            LDSM_X2(bh, bH + nstep + boff);
            LDSM_X2(bl, bL + nstep + boff);
            MMA_BF16(acc[0][nt], ah0, bh);
            MMA_BF16(acc[0][nt], ah0, bl);
            MMA_BF16(acc[0][nt], al0, bh);
            MMA_BF16(acc[1][nt], ah1, bh);
            MMA_BF16(acc[1][nt], ah1, bl);
            MMA_BF16(acc[1][nt], al1, bh);
        }
    }

    // ---- epilogue: read deg first (both n-warps), sync, then write + reset
    int rr[2][2];
    float idv[2][2];
    #pragma unroll
    for (int mt = 0; mt < 2; mt++) {
        int r1 = r0 + mwid * 32 + mt * 16 + (lane >> 2);
        int r2 = r1 + 8;
        rr[mt][0] = r1; rr[mt][1] = r2;
        idv[mt][0] = (r1 < N_NODES) ? 1.0f / (s_deg[r1] + 1.0f) : 0.f;
        idv[mt][1] = (r2 < N_NODES) ? 1.0f / (s_deg[r2] + 1.0f) : 0.f;
    }
    __syncthreads();   // all deg reads complete before any reset

    #pragma unroll
    for (int mt = 0; mt < 2; mt++) {
        #pragma unroll
        for (int h = 0; h < 2; h++) {
            int r = rr[mt][h];
            if (r >= N_NODES) continue;
            float id = idv[mt][h];
            if (nwid == 0 && (lane & 3) == 0) {
                s_dis[r] = sqrtf(id);
                s_deg[r] = 0.0f;
            }
            #pragma unroll
            for (int nt = 0; nt < 4; nt++) {
                int n0 = nwid * 32 + nt * 8 + (lane & 3) * 2;
                float2 bv = *(const float2*)&bias[n0];
                float2 xp = make_float2(acc[mt][nt][h * 2], acc[mt][nt][h * 2 + 1]);
                *(float2*)&s_xp[(size_t)r * F_OUT + n0] = xp;
                *(float2*)&out[(size_t)r * F_OUT + n0] =
                    make_float2(xp.x * id + bv.x, xp.y * id + bv.y);
            }
        }
    }
}

// ---------------------------------------------------------------------------
// Edge aggregation: out[col] += dis[row]*sigmoid(ew)*dis[col] * xp[row]
// 8 edges per warp: 16 lanes/edge group, 4 edges per group (MLP=4 gathers),
// float4 RED scatter.
// ---------------------------------------------------------------------------
__global__ __launch_bounds__(256) void k_edge(const int* __restrict__ ei,
                                              const float* __restrict__ ew,
                                              float* __restrict__ out) {
    int gtid = blockIdx.x * blockDim.x + threadIdx.x;
    int lane = threadIdx.x & 31;
    int half = lane >> 4;
    int sub  = lane & 15;
    int ebase = (gtid >> 5) * 8 + half * 4;

    int   rowv[4], colv[4];
    float cf[4];
    #pragma unroll
    for (int j = 0; j < 4; j++) {
        int e = ebase + j;
        rowv[j] = ei[e];
        colv[j] = ei[N_EDGES + e];
        float w = 1.f / (1.f + __expf(-ew[e]));
        cf[j] = s_dis[rowv[j]] * w * s_dis[colv[j]];
    }

    float4 xv[4];
    #pragma unroll
    for (int j = 0; j < 4; j++)
        xv[j] = *(const float4*)&s_xp[(size_t)rowv[j] * F_OUT + sub * 4];

    #pragma unroll
    for (int j = 0; j < 4; j++) {
        float4 m = make_float4(xv[j].x * cf[j], xv[j].y * cf[j],
                               xv[j].z * cf[j], xv[j].w * cf[j]);
        atomicAdd((float4*)&out[(size_t)colv[j] * F_OUT + sub * 4], m);
    }
}

// ---------------------------------------------------------------------------
extern "C" void kernel_launch(void* const* d_in, const int* in_sizes, int n_in,
                              void* d_out, int out_size) {
    const float* x    = (const float*)d_in[0];
    const int*   ei   = (const int*)d_in[1];
    const float* W    = (const float*)d_in[2];
    const float* bias = (const float*)d_in[3];
    const float* ew   = (const float*)d_in[4];
    const float* u    = (const float*)d_in[5];
    float* out = (float*)d_out;

    cudaFuncSetAttribute(k_gemm, cudaFuncAttributeMaxDynamicSharedMemorySize, SM_TOTAL);

    k_deg_acc<<<(N_EDGES + 255) / 256, 256>>>(ei, ew);
    k_gemm<<<(N_NODES + TM - 1) / TM, 256, SM_TOTAL>>>(x, W, bias, u, out);
    // 8 edges per warp: 600000/8 = 75000 warps / 8 per block = 9375 blocks
    k_edge<<<9375, 256>>>(ei, ew, out);
}

// round 12
// speedup vs baseline: 1.2232x; 1.2232x over previous
#include <cuda_runtime.h>
#include <cuda_bf16.h>
#include <cstdint>

#define N_NODES 100000
#define N_EDGES 600000
#define F_IN 128
#define F_OUT 64
#define TM 128
#define AP 136                 // smem pitch in bf16 (272B rows: 16B-aligned, conflict-free)

// Scratch (no allocation allowed in kernel_launch)
__device__ float s_xp[(size_t)N_NODES * F_OUT];
__device__ float s_deg[N_NODES];   // zero-init; gemm epilogue re-zeroes after use
__device__ float s_dis[N_NODES];
__device__ float s_inv_sigma;

// dynamic smem byte offsets for k_gemm
#define SM_AHI 0                          // 128*136*2 = 34816
#define SM_ALO 34816
#define SM_BHI 69632                      // 64*136*2 = 17408
#define SM_BLO 87040
#define SM_TOTAL 104448

__device__ __forceinline__ uint32_t smem_u32(const void* p) {
    uint32_t a;
    asm("{ .reg .u64 t; cvta.to.shared.u64 t, %1; cvt.u32.u64 %0, t; }" : "=r"(a) : "l"(p));
    return a;
}

#define LDSM_X4(r, addr) \
    asm volatile("ldmatrix.sync.aligned.m8n8.x4.shared.b16 {%0,%1,%2,%3}, [%4];" \
        : "=r"((r)[0]), "=r"((r)[1]), "=r"((r)[2]), "=r"((r)[3]) : "r"(addr))
#define LDSM_X2(r, addr) \
    asm volatile("ldmatrix.sync.aligned.m8n8.x2.shared.b16 {%0,%1}, [%2];" \
        : "=r"((r)[0]), "=r"((r)[1]) : "r"(addr))
#define MMA_BF16(c, a, b) \
    asm volatile("mma.sync.aligned.m16n8k16.row.col.f32.bf16.bf16.f32 " \
        "{%0,%1,%2,%3}, {%4,%5,%6,%7}, {%8,%9}, {%0,%1,%2,%3};" \
        : "+f"((c)[0]), "+f"((c)[1]), "+f"((c)[2]), "+f"((c)[3]) \
        : "r"((a)[0]), "r"((a)[1]), "r"((a)[2]), "r"((a)[3]), "r"((b)[0]), "r"((b)[1]))

// ---------------------------------------------------------------------------
// sigma = ||W (W^T u / ||W^T u||)||  ->  store 1/sigma (single block)
// ---------------------------------------------------------------------------
__global__ void k_sigma(const float* __restrict__ W, const float* __restrict__ u) {
    __shared__ float v[F_OUT];
    __shared__ float red[128];
    __shared__ float n1_s;
    int t = threadIdx.x;

    if (t < F_OUT) {
        float s = 0.f;
        for (int i = 0; i < F_IN; i++) s += W[i * F_OUT + t] * u[i];
        v[t] = s;
    }
    __syncthreads();

    red[t] = (t < F_OUT) ? v[t] * v[t] : 0.f;
    __syncthreads();
    for (int s = 64; s > 0; s >>= 1) {
        if (t < s) red[t] += red[t + s];
        __syncthreads();
    }
    if (t == 0) n1_s = sqrtf(red[0]);
    __syncthreads();

    float g = 0.f;
    for (int j = 0; j < F_OUT; j++) g += W[t * F_OUT + j] * v[j];
    red[t] = g * g;
    __syncthreads();
    for (int s = 64; s > 0; s >>= 1) {
        if (t < s) red[t] += red[t + s];
        __syncthreads();
    }
    if (t == 0) s_inv_sigma = n1_s / sqrtf(red[0]);
}

// ---------------------------------------------------------------------------
__global__ void k_deg_acc(const int* __restrict__ ei,
                          const float* __restrict__ ew) {
    int e = blockIdx.x * blockDim.x + threadIdx.x;
    if (e < N_EDGES) {
        int col = ei[N_EDGES + e];
        float w = 1.f / (1.f + __expf(-ew[e]));
        atomicAdd(&s_deg[col], w);
    }
}

// ---------------------------------------------------------------------------
// Tensor GEMM (mma.sync bf16 3-term split) + fused epilogue:
//   out = xp/(deg+1) + bias ; stash xp ; s_dis = rsqrt(deg+1) ; reset s_deg.
// Block: 128 rows x 64 cols, 256 threads (8 warps: 4 m-groups x 2 n-groups).
// ---------------------------------------------------------------------------
__global__ __launch_bounds__(256) void k_gemm(const float* __restrict__ x,
                                              const float* __restrict__ W,
                                              const float* __restrict__ bias,
                                              float* __restrict__ out) {
    extern __shared__ char smem[];
    uint32_t sb = smem_u32(smem);
    int tid = threadIdx.x;
    int wid = tid >> 5;
    int lane = tid & 31;
    int mwid = wid & 3;       // m-group: 32 rows
    int nwid = wid >> 2;      // n-group: 32 cols
    int r0 = blockIdx.x * TM;

    float inv_sigma = s_inv_sigma;

    // ---- A: x[r0:r0+128, :] -> bf16 hi/lo into padded smem [128][AP]
    __nv_bfloat16* Ahi = (__nv_bfloat16*)(smem + SM_AHI);
    __nv_bfloat16* Alo = (__nv_bfloat16*)(smem + SM_ALO);
    #pragma unroll 4
    for (int it = 0; it < 16; it++) {
        int idx = it * 256 + tid;        // float4 slot, 4096 total
        int row = idx >> 5;
        int k4 = (idx & 31) * 4;
        int grow = r0 + row;
        float4 v = make_float4(0.f, 0.f, 0.f, 0.f);
        if (grow < N_NODES) v = *(const float4*)&x[(size_t)grow * F_IN + k4];

        float fv[4] = {v.x, v.y, v.z, v.w};
        __nv_bfloat16 h[4], l[4];
        #pragma unroll
        for (int j = 0; j < 4; j++) {
            h[j] = __float2bfloat16_rn(fv[j]);
            l[j] = __float2bfloat16_rn(fv[j] - __bfloat162float(h[j]));
        }
        int base = row * AP + k4;
        *(__nv_bfloat162*)&Ahi[base]     = __nv_bfloat162(h[0], h[1]);
        *(__nv_bfloat162*)&Ahi[base + 2] = __nv_bfloat162(h[2], h[3]);
        *(__nv_bfloat162*)&Alo[base]     = __nv_bfloat162(l[0], l[1]);
        *(__nv_bfloat162*)&Alo[base + 2] = __nv_bfloat162(l[2], l[3]);
    }

    // ---- B: B[n][k] = bf16(W[k][n] * inv_sigma); thread: k=tid>>1, half n range
    __nv_bfloat16* Bhi = (__nv_bfloat16*)(smem + SM_BHI);
    __nv_bfloat16* Blo = (__nv_bfloat16*)(smem + SM_BLO);
    {
        int k = tid >> 1;
        int n4base = (tid & 1) * 8;
        const float4* wr = (const float4*)(W + (size_t)k * F_OUT);
        #pragma unroll
        for (int n4i = 0; n4i < 8; n4i++) {
            int n4 = n4base + n4i;
            float4 wv = wr[n4];
            float vv[4] = {wv.x * inv_sigma, wv.y * inv_sigma,
                           wv.z * inv_sigma, wv.w * inv_sigma};
            #pragma unroll
            for (int j = 0; j < 4; j++) {
                int n = n4 * 4 + j;
                __nv_bfloat16 h = __float2bfloat16_rn(vv[j]);
                __nv_bfloat16 l = __float2bfloat16_rn(vv[j] - __bfloat162float(h));
                Bhi[n * AP + k] = h;
                Blo[n * AP + k] = l;
            }
        }
    }
    __syncthreads();

    // ---- fragment mainloop: each warp 32 rows (2 m16) x 32 cols (4 n8)
    float acc[2][4][4];
    #pragma unroll
    for (int mt = 0; mt < 2; mt++)
        #pragma unroll
        for (int nt = 0; nt < 4; nt++)
            #pragma unroll
            for (int j = 0; j < 4; j++) acc[mt][nt][j] = 0.f;

    int lm = lane & 15;
    int lk = (lane >> 4) * 8;
    int bn = lane & 7;
    int bk = ((lane >> 3) & 1) * 8;

    uint32_t aH0 = sb + SM_AHI + (uint32_t)(mwid * 32 + lm) * AP * 2;
    uint32_t aH1 = aH0 + 16u * AP * 2;
    uint32_t aL0 = sb + SM_ALO + (uint32_t)(mwid * 32 + lm) * AP * 2;
    uint32_t aL1 = aL0 + 16u * AP * 2;
    uint32_t bH  = sb + SM_BHI + (uint32_t)(nwid * 32 + bn) * AP * 2;
    uint32_t bL  = sb + SM_BLO + (uint32_t)(nwid * 32 + bn) * AP * 2;

    #pragma unroll
    for (int ks = 0; ks < 8; ks++) {
        int kb = ks * 16;
        uint32_t aoff = (uint32_t)(kb + lk) * 2;
        uint32_t boff = (uint32_t)(kb + bk) * 2;

        uint32_t ah0[4], ah1[4], al0[4], al1[4];
        LDSM_X4(ah0, aH0 + aoff);
        LDSM_X4(ah1, aH1 + aoff);
        LDSM_X4(al0, aL0 + aoff);
        LDSM_X4(al1, aL1 + aoff);

        #pragma unroll
        for (int nt = 0; nt < 4; nt++) {
            uint32_t bh[2], bl[2];
            uint32_t nstep = (uint32_t)(nt * 8) * AP * 2;
            LDSM_X2(bh, bH + nstep + boff);
            LDSM_X2(bl, bL + nstep + boff);
            MMA_BF16(acc[0][nt], ah0, bh);
            MMA_BF16(acc[0][nt], ah0, bl);
            MMA_BF16(acc[0][nt], al0, bh);
            MMA_BF16(acc[1][nt], ah1, bh);
            MMA_BF16(acc[1][nt], ah1, bl);
            MMA_BF16(acc[1][nt], al1, bh);
        }
    }

    // ---- epilogue: read deg first (both n-warps), sync, then write + reset
    int rr[2][2];
    float idv[2][2];
    #pragma unroll
    for (int mt = 0; mt < 2; mt++) {
        int r1 = r0 + mwid * 32 + mt * 16 + (lane >> 2);
        int r2 = r1 + 8;
        rr[mt][0] = r1; rr[mt][1] = r2;
        idv[mt][0] = (r1 < N_NODES) ? 1.0f / (s_deg[r1] + 1.0f) : 0.f;
        idv[mt][1] = (r2 < N_NODES) ? 1.0f / (s_deg[r2] + 1.0f) : 0.f;
    }
    __syncthreads();   // all deg reads complete before any reset

    #pragma unroll
    for (int mt = 0; mt < 2; mt++) {
        #pragma unroll
        for (int h = 0; h < 2; h++) {
            int r = rr[mt][h];
            if (r >= N_NODES) continue;
            float id = idv[mt][h];
            if (nwid == 0 && (lane & 3) == 0) {
                s_dis[r] = sqrtf(id);
                s_deg[r] = 0.0f;
            }
            #pragma unroll
            for (int nt = 0; nt < 4; nt++) {
                int n0 = nwid * 32 + nt * 8 + (lane & 3) * 2;
                float2 bv = *(const float2*)&bias[n0];
                float2 xp = make_float2(acc[mt][nt][h * 2], acc[mt][nt][h * 2 + 1]);
                *(float2*)&s_xp[(size_t)r * F_OUT + n0] = xp;
                *(float2*)&out[(size_t)r * F_OUT + n0] =
                    make_float2(xp.x * id + bv.x, xp.y * id + bv.y);
            }
        }
    }
}

// ---------------------------------------------------------------------------
// Edge aggregation: out[col] += dis[row]*sigmoid(ew)*dis[col] * xp[row]
// 4 edges per warp: 16 lanes/edge, 2 edges per lane group (MLP=2 gathers),
// float4 RED scatter.  (Measured-best configuration from R10.)
// ---------------------------------------------------------------------------
__global__ __launch_bounds__(256) void k_edge(const int* __restrict__ ei,
                                              const float* __restrict__ ew,
                                              float* __restrict__ out) {
    int gtid = blockIdx.x * blockDim.x + threadIdx.x;
    int lane = threadIdx.x & 31;
    int half = lane >> 4;
    int sub  = lane & 15;
    int ebase = (gtid >> 5) * 4 + half * 2;

    int   rowv[2], colv[2];
    float cf[2];
    #pragma unroll
    for (int j = 0; j < 2; j++) {
        int e = ebase + j;
        rowv[j] = ei[e];
        colv[j] = ei[N_EDGES + e];
        float w = 1.f / (1.f + __expf(-ew[e]));
        cf[j] = s_dis[rowv[j]] * w * s_dis[colv[j]];
    }

    float4 xv0 = *(const float4*)&s_xp[(size_t)rowv[0] * F_OUT + sub * 4];
    float4 xv1 = *(const float4*)&s_xp[(size_t)rowv[1] * F_OUT + sub * 4];

    float4 m0 = make_float4(xv0.x * cf[0], xv0.y * cf[0], xv0.z * cf[0], xv0.w * cf[0]);
    atomicAdd((float4*)&out[(size_t)colv[0] * F_OUT + sub * 4], m0);
    float4 m1 = make_float4(xv1.x * cf[1], xv1.y * cf[1], xv1.z * cf[1], xv1.w * cf[1]);
    atomicAdd((float4*)&out[(size_t)colv[1] * F_OUT + sub * 4], m1);
}

// ---------------------------------------------------------------------------
extern "C" void kernel_launch(void* const* d_in, const int* in_sizes, int n_in,
                              void* d_out, int out_size) {
    const float* x    = (const float*)d_in[0];
    const int*   ei   = (const int*)d_in[1];
    const float* W    = (const float*)d_in[2];
    const float* bias = (const float*)d_in[3];
    const float* ew   = (const float*)d_in[4];
    const float* u    = (const float*)d_in[5];
    float* out = (float*)d_out;

    cudaFuncSetAttribute(k_gemm, cudaFuncAttributeMaxDynamicSharedMemorySize, SM_TOTAL);

    k_sigma<<<1, 128>>>(W, u);
    k_deg_acc<<<(N_EDGES + 255) / 256, 256>>>(ei, ew);
    k_gemm<<<(N_NODES + TM - 1) / TM, 256, SM_TOTAL>>>(x, W, bias, out);
    // 4 edges per warp: 600000/4 = 150000 warps / 8 per block = 18750 blocks
    k_edge<<<18750, 256>>>(ei, ew, out);
}

// round 13
// speedup vs baseline: 1.2457x; 1.0183x over previous
#include <cuda_runtime.h>
#include <cuda_fp16.h>
#include <cstdint>

#define N_NODES 100000
#define N_EDGES 600000
#define F_IN 128
#define F_OUT 64
#define TM 128
#define AP 136                 // smem pitch in fp16 (272B rows: 16B-aligned, conflict-free)

// Scratch (no allocation allowed in kernel_launch)
__device__ float s_xp[(size_t)N_NODES * F_OUT];
__device__ float s_deg[N_NODES];   // zero-init; gemm epilogue re-zeroes after use
__device__ float s_dis[N_NODES];
__device__ float s_inv_sigma;

// dynamic smem byte offsets for k_gemm
#define SM_AHI 0                          // 128*136*2 = 34816
#define SM_ALO 34816
#define SM_BHI 69632                      // 64*136*2 = 17408
#define SM_BLO 87040
#define SM_TOTAL 104448

__device__ __forceinline__ uint32_t smem_u32(const void* p) {
    uint32_t a;
    asm("{ .reg .u64 t; cvta.to.shared.u64 t, %1; cvt.u32.u64 %0, t; }" : "=r"(a) : "l"(p));
    return a;
}

#define LDSM_X4(r, addr) \
    asm volatile("ldmatrix.sync.aligned.m8n8.x4.shared.b16 {%0,%1,%2,%3}, [%4];" \
        : "=r"((r)[0]), "=r"((r)[1]), "=r"((r)[2]), "=r"((r)[3]) : "r"(addr))
#define LDSM_X2(r, addr) \
    asm volatile("ldmatrix.sync.aligned.m8n8.x2.shared.b16 {%0,%1}, [%2];" \
        : "=r"((r)[0]), "=r"((r)[1]) : "r"(addr))
#define MMA_F16(c, a, b) \
    asm volatile("mma.sync.aligned.m16n8k16.row.col.f32.f16.f16.f32 " \
        "{%0,%1,%2,%3}, {%4,%5,%6,%7}, {%8,%9}, {%0,%1,%2,%3};" \
        : "+f"((c)[0]), "+f"((c)[1]), "+f"((c)[2]), "+f"((c)[3]) \
        : "r"((a)[0]), "r"((a)[1]), "r"((a)[2]), "r"((a)[3]), "r"((b)[0]), "r"((b)[1]))

// ---------------------------------------------------------------------------
// sigma = ||W (W^T u / ||W^T u||)||  ->  store 1/sigma (single block)
// ---------------------------------------------------------------------------
__global__ void k_sigma(const float* __restrict__ W, const float* __restrict__ u) {
    __shared__ float v[F_OUT];
    __shared__ float red[128];
    __shared__ float n1_s;
    int t = threadIdx.x;

    if (t < F_OUT) {
        float s = 0.f;
        for (int i = 0; i < F_IN; i++) s += W[i * F_OUT + t] * u[i];
        v[t] = s;
    }
    __syncthreads();

    red[t] = (t < F_OUT) ? v[t] * v[t] : 0.f;
    __syncthreads();
    for (int s = 64; s > 0; s >>= 1) {
        if (t < s) red[t] += red[t + s];
        __syncthreads();
    }
    if (t == 0) n1_s = sqrtf(red[0]);
    __syncthreads();

    float g = 0.f;
    for (int j = 0; j < F_OUT; j++) g += W[t * F_OUT + j] * v[j];
    red[t] = g * g;
    __syncthreads();
    for (int s = 64; s > 0; s >>= 1) {
        if (t < s) red[t] += red[t + s];
        __syncthreads();
    }
    if (t == 0) s_inv_sigma = n1_s / sqrtf(red[0]);
}

// ---------------------------------------------------------------------------
// deg accumulation, 4 edges per thread (600000 % 4 == 0)
// ---------------------------------------------------------------------------
__global__ void k_deg_acc(const int* __restrict__ ei,
                          const float* __restrict__ ew) {
    int t = blockIdx.x * blockDim.x + threadIdx.x;
    if (t * 4 >= N_EDGES) return;
    int4   cols = *(const int4*)&ei[N_EDGES + t * 4];
    float4 wv   = *(const float4*)&ew[t * 4];
    atomicAdd(&s_deg[cols.x], 1.f / (1.f + __expf(-wv.x)));
    atomicAdd(&s_deg[cols.y], 1.f / (1.f + __expf(-wv.y)));
    atomicAdd(&s_deg[cols.z], 1.f / (1.f + __expf(-wv.z)));
    atomicAdd(&s_deg[cols.w], 1.f / (1.f + __expf(-wv.w)));
}

// ---------------------------------------------------------------------------
// Tensor GEMM (mma.sync fp16 3-term split) + fused epilogue:
//   xp = Ahi*Bhi + Ahi*Blo + Alo*Bhi   (A,B split to fp16 hi/lo; err ~2^-22)
//   out = xp/(deg+1) + bias ; stash xp ; s_dis = rsqrt(deg+1) ; reset s_deg.
// Block: 128 rows x 64 cols, 256 threads (8 warps: 4 m-groups x 2 n-groups).
// ---------------------------------------------------------------------------
__global__ __launch_bounds__(256) void k_gemm(const float* __restrict__ x,
                                              const float* __restrict__ W,
                                              const float* __restrict__ bias,
                                              float* __restrict__ out) {
    extern __shared__ char smem[];
    uint32_t sb = smem_u32(smem);
    int tid = threadIdx.x;
    int wid = tid >> 5;
    int lane = tid & 31;
    int mwid = wid & 3;       // m-group: 32 rows
    int nwid = wid >> 2;      // n-group: 32 cols
    int r0 = blockIdx.x * TM;

    float inv_sigma = s_inv_sigma;

    // ---- A: x[r0:r0+128, :] -> fp16 hi/lo into padded smem [128][AP]
    __half* Ahi = (__half*)(smem + SM_AHI);
    __half* Alo = (__half*)(smem + SM_ALO);
    #pragma unroll 4
    for (int it = 0; it < 16; it++) {
        int idx = it * 256 + tid;        // float4 slot, 4096 total
        int row = idx >> 5;
        int k4 = (idx & 31) * 4;
        int grow = r0 + row;
        float4 v = make_float4(0.f, 0.f, 0.f, 0.f);
        if (grow < N_NODES) v = *(const float4*)&x[(size_t)grow * F_IN + k4];

        float fv[4] = {v.x, v.y, v.z, v.w};
        __half h[4], l[4];
        #pragma unroll
        for (int j = 0; j < 4; j++) {
            h[j] = __float2half_rn(fv[j]);
            l[j] = __float2half_rn(fv[j] - __half2float(h[j]));
        }
        int base = row * AP + k4;
        *(__half2*)&Ahi[base]     = __half2(h[0], h[1]);
        *(__half2*)&Ahi[base + 2] = __half2(h[2], h[3]);
        *(__half2*)&Alo[base]     = __half2(l[0], l[1]);
        *(__half2*)&Alo[base + 2] = __half2(l[2], l[3]);
    }

    // ---- B: B[n][k] = fp16(W[k][n] * inv_sigma); thread: k=tid>>1, half n range
    __half* Bhi = (__half*)(smem + SM_BHI);
    __half* Blo = (__half*)(smem + SM_BLO);
    {
        int k = tid >> 1;
        int n4base = (tid & 1) * 8;
        const float4* wr = (const float4*)(W + (size_t)k * F_OUT);
        #pragma unroll
        for (int n4i = 0; n4i < 8; n4i++) {
            int n4 = n4base + n4i;
            float4 wv = wr[n4];
            float vv[4] = {wv.x * inv_sigma, wv.y * inv_sigma,
                           wv.z * inv_sigma, wv.w * inv_sigma};
            #pragma unroll
            for (int j = 0; j < 4; j++) {
                int n = n4 * 4 + j;
                __half h = __float2half_rn(vv[j]);
                __half l = __float2half_rn(vv[j] - __half2float(h));
                Bhi[n * AP + k] = h;
                Blo[n * AP + k] = l;
            }
        }
    }
    __syncthreads();

    // ---- fragment mainloop: each warp 32 rows (2 m16) x 32 cols (4 n8)
    float acc[2][4][4];
    #pragma unroll
    for (int mt = 0; mt < 2; mt++)
        #pragma unroll
        for (int nt = 0; nt < 4; nt++)
            #pragma unroll
            for (int j = 0; j < 4; j++) acc[mt][nt][j] = 0.f;

    int lm = lane & 15;
    int lk = (lane >> 4) * 8;
    int bn = lane & 7;
    int bk = ((lane >> 3) & 1) * 8;

    uint32_t aH0 = sb + SM_AHI + (uint32_t)(mwid * 32 + lm) * AP * 2;
    uint32_t aH1 = aH0 + 16u * AP * 2;
    uint32_t aL0 = sb + SM_ALO + (uint32_t)(mwid * 32 + lm) * AP * 2;
    uint32_t aL1 = aL0 + 16u * AP * 2;
    uint32_t bH  = sb + SM_BHI + (uint32_t)(nwid * 32 + bn) * AP * 2;
    uint32_t bL  = sb + SM_BLO + (uint32_t)(nwid * 32 + bn) * AP * 2;

    #pragma unroll
    for (int ks = 0; ks < 8; ks++) {
        int kb = ks * 16;
        uint32_t aoff = (uint32_t)(kb + lk) * 2;
        uint32_t boff = (uint32_t)(kb + bk) * 2;

        uint32_t ah0[4], ah1[4], al0[4], al1[4];
        LDSM_X4(ah0, aH0 + aoff);
        LDSM_X4(ah1, aH1 + aoff);
        LDSM_X4(al0, aL0 + aoff);
        LDSM_X4(al1, aL1 + aoff);

        #pragma unroll
        for (int nt = 0; nt < 4; nt++) {
            uint32_t bh[2], bl[2];
            uint32_t nstep = (uint32_t)(nt * 8) * AP * 2;
            LDSM_X2(bh, bH + nstep + boff);
            LDSM_X2(bl, bL + nstep + boff);
            MMA_F16(acc[0][nt], ah0, bh);
            MMA_F16(acc[0][nt], ah0, bl);
            MMA_F16(acc[0][nt], al0, bh);
            MMA_F16(acc[1][nt], ah1, bh);
            MMA_F16(acc[1][nt], ah1, bl);
            MMA_F16(acc[1][nt], al1, bh);
        }
    }

    // ---- epilogue: read deg first (both n-warps), sync, then write + reset
    int rr[2][2];
    float idv[2][2];
    #pragma unroll
    for (int mt = 0; mt < 2; mt++) {
        int r1 = r0 + mwid * 32 + mt * 16 + (lane >> 2);
        int r2 = r1 + 8;
        rr[mt][0] = r1; rr[mt][1] = r2;
        idv[mt][0] = (r1 < N_NODES) ? 1.0f / (s_deg[r1] + 1.0f) : 0.f;
        idv[mt][1] = (r2 < N_NODES) ? 1.0f / (s_deg[r2] + 1.0f) : 0.f;
    }
    __syncthreads();   // all deg reads complete before any reset

    #pragma unroll
    for (int mt = 0; mt < 2; mt++) {
        #pragma unroll
        for (int h = 0; h < 2; h++) {
            int r = rr[mt][h];
            if (r >= N_NODES) continue;
            float id = idv[mt][h];
            if (nwid == 0 && (lane & 3) == 0) {
                s_dis[r] = sqrtf(id);
                s_deg[r] = 0.0f;
            }
            #pragma unroll
            for (int nt = 0; nt < 4; nt++) {
                int n0 = nwid * 32 + nt * 8 + (lane & 3) * 2;
                float2 bv = *(const float2*)&bias[n0];
                float2 xp = make_float2(acc[mt][nt][h * 2], acc[mt][nt][h * 2 + 1]);
                *(float2*)&s_xp[(size_t)r * F_OUT + n0] = xp;
                *(float2*)&out[(size_t)r * F_OUT + n0] =
                    make_float2(xp.x * id + bv.x, xp.y * id + bv.y);
            }
        }
    }
}

// ---------------------------------------------------------------------------
// Edge aggregation: out[col] += dis[row]*sigmoid(ew)*dis[col] * xp[row]
// 4 edges per warp: 16 lanes/edge, 2 edges per lane group (MLP=2 gathers),
// float4 RED scatter.  (Measured-best configuration.)
// ---------------------------------------------------------------------------
__global__ __launch_bounds__(256) void k_edge(const int* __restrict__ ei,
                                              const float* __restrict__ ew,
                                              float* __restrict__ out) {
    int gtid = blockIdx.x * blockDim.x + threadIdx.x;
    int lane = threadIdx.x & 31;
    int half = lane >> 4;
    int sub  = lane & 15;
    int ebase = (gtid >> 5) * 4 + half * 2;

    int   rowv[2], colv[2];
    float cf[2];
    #pragma unroll
    for (int j = 0; j < 2; j++) {
        int e = ebase + j;
        rowv[j] = ei[e];
        colv[j] = ei[N_EDGES + e];
        float w = 1.f / (1.f + __expf(-ew[e]));
        cf[j] = s_dis[rowv[j]] * w * s_dis[colv[j]];
    }

    float4 xv0 = *(const float4*)&s_xp[(size_t)rowv[0] * F_OUT + sub * 4];
    float4 xv1 = *(const float4*)&s_xp[(size_t)rowv[1] * F_OUT + sub * 4];

    float4 m0 = make_float4(xv0.x * cf[0], xv0.y * cf[0], xv0.z * cf[0], xv0.w * cf[0]);
    atomicAdd((float4*)&out[(size_t)colv[0] * F_OUT + sub * 4], m0);
    float4 m1 = make_float4(xv1.x * cf[1], xv1.y * cf[1], xv1.z * cf[1], xv1.w * cf[1]);
    atomicAdd((float4*)&out[(size_t)colv[1] * F_OUT + sub * 4], m1);
}

// ---------------------------------------------------------------------------
extern "C" void kernel_launch(void* const* d_in, const int* in_sizes, int n_in,
                              void* d_out, int out_size) {
    const float* x    = (const float*)d_in[0];
    const int*   ei   = (const int*)d_in[1];
    const float* W    = (const float*)d_in[2];
    const float* bias = (const float*)d_in[3];
    const float* ew   = (const float*)d_in[4];
    const float* u    = (const float*)d_in[5];
    float* out = (float*)d_out;

    cudaFuncSetAttribute(k_gemm, cudaFuncAttributeMaxDynamicSharedMemorySize, SM_TOTAL);

    k_sigma<<<1, 128>>>(W, u);
    k_deg_acc<<<(N_EDGES / 4 + 255) / 256, 256>>>(ei, ew);
    k_gemm<<<(N_NODES + TM - 1) / TM, 256, SM_TOTAL>>>(x, W, bias, out);
    // 4 edges per warp: 600000/4 = 150000 warps / 8 per block = 18750 blocks
    k_edge<<<18750, 256>>>(ei, ew, out);
}

// round 14
// speedup vs baseline: 1.3642x; 1.0951x over previous
#include <cuda_runtime.h>
#include <cuda_fp16.h>
#include <cstdint>

#define N_NODES 100000
#define N_EDGES 600000
#define F_IN 128
#define F_OUT 64
#define TM 128
#define AP 136                 // smem pitch in fp16 (272B rows: 16B-aligned, conflict-free)

// Scratch (no allocation allowed in kernel_launch)
__device__ __half s_xph[(size_t)N_NODES * F_OUT];   // fp16 xp for the edge gather
__device__ float s_deg[N_NODES];   // zero-init; gemm epilogue re-zeroes after use
__device__ float s_dis[N_NODES];
__device__ float s_inv_sigma;

// dynamic smem byte offsets for k_gemm
#define SM_AHI 0                          // 128*136*2 = 34816
#define SM_ALO 34816
#define SM_BHI 69632                      // 64*136*2 = 17408
#define SM_BLO 87040
#define SM_TOTAL 104448

__device__ __forceinline__ uint32_t smem_u32(const void* p) {
    uint32_t a;
    asm("{ .reg .u64 t; cvta.to.shared.u64 t, %1; cvt.u32.u64 %0, t; }" : "=r"(a) : "l"(p));
    return a;
}

#define LDSM_X4(r, addr) \
    asm volatile("ldmatrix.sync.aligned.m8n8.x4.shared.b16 {%0,%1,%2,%3}, [%4];" \
        : "=r"((r)[0]), "=r"((r)[1]), "=r"((r)[2]), "=r"((r)[3]) : "r"(addr))
#define LDSM_X2(r, addr) \
    asm volatile("ldmatrix.sync.aligned.m8n8.x2.shared.b16 {%0,%1}, [%2];" \
        : "=r"((r)[0]), "=r"((r)[1]) : "r"(addr))
#define MMA_F16(c, a, b) \
    asm volatile("mma.sync.aligned.m16n8k16.row.col.f32.f16.f16.f32 " \
        "{%0,%1,%2,%3}, {%4,%5,%6,%7}, {%8,%9}, {%0,%1,%2,%3};" \
        : "+f"((c)[0]), "+f"((c)[1]), "+f"((c)[2]), "+f"((c)[3]) \
        : "r"((a)[0]), "r"((a)[1]), "r"((a)[2]), "r"((a)[3]), "r"((b)[0]), "r"((b)[1]))

// ---------------------------------------------------------------------------
// Fused: blocks [0, G-2] accumulate degree (4 edges/thread);
// block G-1 computes 1/sigma (power-iteration step) with its first 128 threads.
// ---------------------------------------------------------------------------
__global__ void k_deg_sigma(const int* __restrict__ ei,
                            const float* __restrict__ ew,
                            const float* __restrict__ W,
                            const float* __restrict__ u) {
    if (blockIdx.x == gridDim.x - 1) {
        __shared__ float v[F_OUT];
        __shared__ float red[128];
        __shared__ float n1_s;
        int t = threadIdx.x;
        bool act = (t < 128);

        if (t < F_OUT) {
            float s = 0.f;
            for (int i = 0; i < F_IN; i++) s += W[i * F_OUT + t] * u[i];
            v[t] = s;
        }
        __syncthreads();
        if (act) red[t] = (t < F_OUT) ? v[t] * v[t] : 0.f;
        __syncthreads();
        for (int s = 64; s > 0; s >>= 1) {
            if (act && t < s) red[t] += red[t + s];
            __syncthreads();
        }
        if (t == 0) n1_s = sqrtf(red[0]);
        __syncthreads();
        if (act) {
            float g = 0.f;
            for (int j = 0; j < F_OUT; j++) g += W[t * F_OUT + j] * v[j];
            red[t] = g * g;
        }
        __syncthreads();
        for (int s = 64; s > 0; s >>= 1) {
            if (act && t < s) red[t] += red[t + s];
            __syncthreads();
        }
        if (t == 0) s_inv_sigma = n1_s / sqrtf(red[0]);
        return;
    }

    int t = blockIdx.x * blockDim.x + threadIdx.x;
    if (t * 4 >= N_EDGES) return;
    int4   cols = *(const int4*)&ei[N_EDGES + t * 4];
    float4 wv   = *(const float4*)&ew[t * 4];
    atomicAdd(&s_deg[cols.x], 1.f / (1.f + __expf(-wv.x)));
    atomicAdd(&s_deg[cols.y], 1.f / (1.f + __expf(-wv.y)));
    atomicAdd(&s_deg[cols.z], 1.f / (1.f + __expf(-wv.z)));
    atomicAdd(&s_deg[cols.w], 1.f / (1.f + __expf(-wv.w)));
}

// ---------------------------------------------------------------------------
// Tensor GEMM (mma.sync fp16 3-term split) + fused epilogue:
//   xp = Ahi*Bhi + Ahi*Blo + Alo*Bhi   (err ~2^-22)
//   out = xp/(deg+1) + bias (fp32 xp, exact self-loop path)
//   s_xph = fp16(xp)  (edge-gather path) ; s_dis = rsqrt(deg+1) ; reset s_deg.
// Block: 128 rows x 64 cols, 256 threads (8 warps: 4 m-groups x 2 n-groups).
// ---------------------------------------------------------------------------
__global__ __launch_bounds__(256) void k_gemm(const float* __restrict__ x,
                                              const float* __restrict__ W,
                                              const float* __restrict__ bias,
                                              float* __restrict__ out) {
    extern __shared__ char smem[];
    uint32_t sb = smem_u32(smem);
    int tid = threadIdx.x;
    int wid = tid >> 5;
    int lane = tid & 31;
    int mwid = wid & 3;       // m-group: 32 rows
    int nwid = wid >> 2;      // n-group: 32 cols
    int r0 = blockIdx.x * TM;

    float inv_sigma = s_inv_sigma;

    // ---- A: x[r0:r0+128, :] -> fp16 hi/lo into padded smem [128][AP]
    __half* Ahi = (__half*)(smem + SM_AHI);
    __half* Alo = (__half*)(smem + SM_ALO);
    #pragma unroll 4
    for (int it = 0; it < 16; it++) {
        int idx = it * 256 + tid;        // float4 slot, 4096 total
        int row = idx >> 5;
        int k4 = (idx & 31) * 4;
        int grow = r0 + row;
        float4 v = make_float4(0.f, 0.f, 0.f, 0.f);
        if (grow < N_NODES) v = *(const float4*)&x[(size_t)grow * F_IN + k4];

        float fv[4] = {v.x, v.y, v.z, v.w};
        __half h[4], l[4];
        #pragma unroll
        for (int j = 0; j < 4; j++) {
            h[j] = __float2half_rn(fv[j]);
            l[j] = __float2half_rn(fv[j] - __half2float(h[j]));
        }
        int base = row * AP + k4;
        *(__half2*)&Ahi[base]     = __half2(h[0], h[1]);
        *(__half2*)&Ahi[base + 2] = __half2(h[2], h[3]);
        *(__half2*)&Alo[base]     = __half2(l[0], l[1]);
        *(__half2*)&Alo[base + 2] = __half2(l[2], l[3]);
    }

    // ---- B: B[n][k] = fp16(W[k][n] * inv_sigma); thread: k=tid>>1, half n range
    __half* Bhi = (__half*)(smem + SM_BHI);
    __half* Blo = (__half*)(smem + SM_BLO);
    {
        int k = tid >> 1;
        int n4base = (tid & 1) * 8;
        const float4* wr = (const float4*)(W + (size_t)k * F_OUT);
        #pragma unroll
        for (int n4i = 0; n4i < 8; n4i++) {
            int n4 = n4base + n4i;
            float4 wv = wr[n4];
            float vv[4] = {wv.x * inv_sigma, wv.y * inv_sigma,
                           wv.z * inv_sigma, wv.w * inv_sigma};
            #pragma unroll
            for (int j = 0; j < 4; j++) {
                int n = n4 * 4 + j;
                __half h = __float2half_rn(vv[j]);
                __half l = __float2half_rn(vv[j] - __half2float(h));
                Bhi[n * AP + k] = h;
                Blo[n * AP + k] = l;
            }
        }
    }
    __syncthreads();

    // ---- fragment mainloop: each warp 32 rows (2 m16) x 32 cols (4 n8)
    float acc[2][4][4];
    #pragma unroll
    for (int mt = 0; mt < 2; mt++)
        #pragma unroll
        for (int nt = 0; nt < 4; nt++)
            #pragma unroll
            for (int j = 0; j < 4; j++) acc[mt][nt][j] = 0.f;

    int lm = lane & 15;
    int lk = (lane >> 4) * 8;
    int bn = lane & 7;
    int bk = ((lane >> 3) & 1) * 8;

    uint32_t aH0 = sb + SM_AHI + (uint32_t)(mwid * 32 + lm) * AP * 2;
    uint32_t aH1 = aH0 + 16u * AP * 2;
    uint32_t aL0 = sb + SM_ALO + (uint32_t)(mwid * 32 + lm) * AP * 2;
    uint32_t aL1 = aL0 + 16u * AP * 2;
    uint32_t bH  = sb + SM_BHI + (uint32_t)(nwid * 32 + bn) * AP * 2;
    uint32_t bL  = sb + SM_BLO + (uint32_t)(nwid * 32 + bn) * AP * 2;

    #pragma unroll
    for (int ks = 0; ks < 8; ks++) {
        int kb = ks * 16;
        uint32_t aoff = (uint32_t)(kb + lk) * 2;
        uint32_t boff = (uint32_t)(kb + bk) * 2;

        uint32_t ah0[4], ah1[4], al0[4], al1[4];
        LDSM_X4(ah0, aH0 + aoff);
        LDSM_X4(ah1, aH1 + aoff);
        LDSM_X4(al0, aL0 + aoff);
        LDSM_X4(al1, aL1 + aoff);

        #pragma unroll
        for (int nt = 0; nt < 4; nt++) {
            uint32_t bh[2], bl[2];
            uint32_t nstep = (uint32_t)(nt * 8) * AP * 2;
            LDSM_X2(bh, bH + nstep + boff);
            LDSM_X2(bl, bL + nstep + boff);
            MMA_F16(acc[0][nt], ah0, bh);
            MMA_F16(acc[0][nt], ah0, bl);
            MMA_F16(acc[0][nt], al0, bh);
            MMA_F16(acc[1][nt], ah1, bh);
            MMA_F16(acc[1][nt], ah1, bl);
            MMA_F16(acc[1][nt], al1, bh);
        }
    }

    // ---- epilogue: read deg first (both n-warps), sync, then write + reset
    int rr[2][2];
    float idv[2][2];
    #pragma unroll
    for (int mt = 0; mt < 2; mt++) {
        int r1 = r0 + mwid * 32 + mt * 16 + (lane >> 2);
        int r2 = r1 + 8;
        rr[mt][0] = r1; rr[mt][1] = r2;
        idv[mt][0] = (r1 < N_NODES) ? 1.0f / (s_deg[r1] + 1.0f) : 0.f;
        idv[mt][1] = (r2 < N_NODES) ? 1.0f / (s_deg[r2] + 1.0f) : 0.f;
    }
    __syncthreads();   // all deg reads complete before any reset

    #pragma unroll
    for (int mt = 0; mt < 2; mt++) {
        #pragma unroll
        for (int h = 0; h < 2; h++) {
            int r = rr[mt][h];
            if (r >= N_NODES) continue;
            float id = idv[mt][h];
            if (nwid == 0 && (lane & 3) == 0) {
                s_dis[r] = sqrtf(id);
                s_deg[r] = 0.0f;
            }
            #pragma unroll
            for (int nt = 0; nt < 4; nt++) {
                int n0 = nwid * 32 + nt * 8 + (lane & 3) * 2;
                float2 bv = *(const float2*)&bias[n0];
                float2 xp = make_float2(acc[mt][nt][h * 2], acc[mt][nt][h * 2 + 1]);
                *(__half2*)&s_xph[(size_t)r * F_OUT + n0] = __floats2half2_rn(xp.x, xp.y);
                *(float2*)&out[(size_t)r * F_OUT + n0] =
                    make_float2(xp.x * id + bv.x, xp.y * id + bv.y);
            }
        }
    }
}

// ---------------------------------------------------------------------------
// Edge aggregation: out[col] += dis[row]*sigmoid(ew)*dis[col] * xp_fp16[row]
// 4 edges per warp: 16 lanes/edge, 2 edges per lane group (MLP=2 gathers).
// Gather is fp16 (128B/edge = 1 line); scatter stays float4 fp32 RED.
// ---------------------------------------------------------------------------
__global__ __launch_bounds__(256) void k_edge(const int* __restrict__ ei,
                                              const float* __restrict__ ew,
                                              float* __restrict__ out) {
    int gtid = blockIdx.x * blockDim.x + threadIdx.x;
    int lane = threadIdx.x & 31;
    int half = lane >> 4;
    int sub  = lane & 15;
    int ebase = (gtid >> 5) * 4 + half * 2;

    int   rowv[2], colv[2];
    float cf[2];
    #pragma unroll
    for (int j = 0; j < 2; j++) {
        int e = ebase + j;
        rowv[j] = ei[e];
        colv[j] = ei[N_EDGES + e];
        float w = 1.f / (1.f + __expf(-ew[e]));
        cf[j] = s_dis[rowv[j]] * w * s_dis[colv[j]];
    }

    uint2 g0 = *(const uint2*)&s_xph[(size_t)rowv[0] * F_OUT + sub * 4];
    uint2 g1 = *(const uint2*)&s_xph[(size_t)rowv[1] * F_OUT + sub * 4];

    float2 a0 = __half22float2(*(__half2*)&g0.x);
    float2 a1 = __half22float2(*(__half2*)&g0.y);
    float4 m0 = make_float4(a0.x * cf[0], a0.y * cf[0], a1.x * cf[0], a1.y * cf[0]);
    atomicAdd((float4*)&out[(size_t)colv[0] * F_OUT + sub * 4], m0);

    float2 b0 = __half22float2(*(__half2*)&g1.x);
    float2 b1 = __half22float2(*(__half2*)&g1.y);
    float4 m1 = make_float4(b0.x * cf[1], b0.y * cf[1], b1.x * cf[1], b1.y * cf[1]);
    atomicAdd((float4*)&out[(size_t)colv[1] * F_OUT + sub * 4], m1);
}

// ---------------------------------------------------------------------------
extern "C" void kernel_launch(void* const* d_in, const int* in_sizes, int n_in,
                              void* d_out, int out_size) {
    const float* x    = (const float*)d_in[0];
    const int*   ei   = (const int*)d_in[1];
    const float* W    = (const float*)d_in[2];
    const float* bias = (const float*)d_in[3];
    const float* ew   = (const float*)d_in[4];
    const float* u    = (const float*)d_in[5];
    float* out = (float*)d_out;

    cudaFuncSetAttribute(k_gemm, cudaFuncAttributeMaxDynamicSharedMemorySize, SM_TOTAL);

    // deg blocks + 1 sigma block
    int deg_blocks = (N_EDGES / 4 + 255) / 256;
    k_deg_sigma<<<deg_blocks + 1, 256>>>(ei, ew, W, u);
    k_gemm<<<(N_NODES + TM - 1) / TM, 256, SM_TOTAL>>>(x, W, bias, out);
    // 4 edges per warp: 600000/4 = 150000 warps / 8 per block = 18750 blocks
    k_edge<<<18750, 256>>>(ei, ew, out);
}

// round 15
// speedup vs baseline: 1.4297x; 1.0481x over previous
#include <cuda_runtime.h>
#include <cuda_fp16.h>
#include <cstdint>

#define N_NODES 100000
#define N_EDGES 600000
#define F_IN 128
#define F_OUT 64
#define TM 128
#define AP 136                 // smem pitch in fp16 (272B rows: 16B-aligned, conflict-free)

// Scratch (no allocation allowed in kernel_launch)
__device__ __half s_xph[(size_t)N_NODES * F_OUT];   // fp16 xp for the edge gather
__device__ float s_deg[N_NODES];   // zero-init; gemm epilogue re-zeroes after use
__device__ float s_dis[N_NODES];
__device__ float s_inv_sigma;

// dynamic smem byte offsets for k_gemm
#define SM_AHI 0                          // 128*136*2 = 34816
#define SM_ALO 34816
#define SM_B   69632                      // 64*136*2 = 17408
#define SM_TOTAL 87040

__device__ __forceinline__ uint32_t smem_u32(const void* p) {
    uint32_t a;
    asm("{ .reg .u64 t; cvta.to.shared.u64 t, %1; cvt.u32.u64 %0, t; }" : "=r"(a) : "l"(p));
    return a;
}

#define LDSM_X4(r, addr) \
    asm volatile("ldmatrix.sync.aligned.m8n8.x4.shared.b16 {%0,%1,%2,%3}, [%4];" \
        : "=r"((r)[0]), "=r"((r)[1]), "=r"((r)[2]), "=r"((r)[3]) : "r"(addr))
#define LDSM_X2(r, addr) \
    asm volatile("ldmatrix.sync.aligned.m8n8.x2.shared.b16 {%0,%1}, [%2];" \
        : "=r"((r)[0]), "=r"((r)[1]) : "r"(addr))
#define MMA_F16(c, a, b) \
    asm volatile("mma.sync.aligned.m16n8k16.row.col.f32.f16.f16.f32 " \
        "{%0,%1,%2,%3}, {%4,%5,%6,%7}, {%8,%9}, {%0,%1,%2,%3};" \
        : "+f"((c)[0]), "+f"((c)[1]), "+f"((c)[2]), "+f"((c)[3]) \
        : "r"((a)[0]), "r"((a)[1]), "r"((a)[2]), "r"((a)[3]), "r"((b)[0]), "r"((b)[1]))

// ---------------------------------------------------------------------------
// Fused: block 0 computes 1/sigma (power-iteration, overlaps with deg work);
// blocks [1, G-1] accumulate degree (4 edges/thread).
// ---------------------------------------------------------------------------
__global__ void k_deg_sigma(const int* __restrict__ ei,
                            const float* __restrict__ ew,
                            const float* __restrict__ W,
                            const float* __restrict__ u) {
    if (blockIdx.x == 0) {
        __shared__ float v[F_OUT];
        __shared__ float red[128];
        __shared__ float n1_s;
        int t = threadIdx.x;
        bool act = (t < 128);

        if (t < F_OUT) {
            float s = 0.f;
            for (int i = 0; i < F_IN; i++) s += W[i * F_OUT + t] * u[i];
            v[t] = s;
        }
        __syncthreads();
        if (act) red[t] = (t < F_OUT) ? v[t] * v[t] : 0.f;
        __syncthreads();
        for (int s = 64; s > 0; s >>= 1) {
            if (act && t < s) red[t] += red[t + s];
            __syncthreads();
        }
        if (t == 0) n1_s = sqrtf(red[0]);
        __syncthreads();
        if (act) {
            float g = 0.f;
            for (int j = 0; j < F_OUT; j++) g += W[t * F_OUT + j] * v[j];
            red[t] = g * g;
        }
        __syncthreads();
        for (int s = 64; s > 0; s >>= 1) {
            if (act && t < s) red[t] += red[t + s];
            __syncthreads();
        }
        if (t == 0) s_inv_sigma = n1_s / sqrtf(red[0]);
        return;
    }

    int t = (blockIdx.x - 1) * blockDim.x + threadIdx.x;
    if (t * 4 >= N_EDGES) return;
    int4   cols = *(const int4*)&ei[N_EDGES + t * 4];
    float4 wv   = *(const float4*)&ew[t * 4];
    atomicAdd(&s_deg[cols.x], 1.f / (1.f + __expf(-wv.x)));
    atomicAdd(&s_deg[cols.y], 1.f / (1.f + __expf(-wv.y)));
    atomicAdd(&s_deg[cols.z], 1.f / (1.f + __expf(-wv.z)));
    atomicAdd(&s_deg[cols.w], 1.f / (1.f + __expf(-wv.w)));
}

// ---------------------------------------------------------------------------
// Tensor GEMM (mma.sync fp16 2-term split) + fused epilogue:
//   xp = Ahi*B + Alo*B = x_exact @ fp16(W/sigma)   (err ~2^-12 from W only)
//   out = xp/(deg+1) + bias (fp32 path)
//   s_xph = fp16(xp) ; s_dis = rsqrt(deg+1) ; reset s_deg.
// Block: 128 rows x 64 cols, 256 threads (8 warps: 4 m-groups x 2 n-groups).
// ---------------------------------------------------------------------------
__global__ __launch_bounds__(256) void k_gemm(const float* __restrict__ x,
                                              const float* __restrict__ W,
                                              const float* __restrict__ bias,
                                              float* __restrict__ out) {
    extern __shared__ char smem[];
    uint32_t sb = smem_u32(smem);
    int tid = threadIdx.x;
    int wid = tid >> 5;
    int lane = tid & 31;
    int mwid = wid & 3;       // m-group: 32 rows
    int nwid = wid >> 2;      // n-group: 32 cols
    int r0 = blockIdx.x * TM;

    float inv_sigma = s_inv_sigma;

    // ---- A: x[r0:r0+128, :] -> fp16 hi/lo into padded smem [128][AP]
    __half* Ahi = (__half*)(smem + SM_AHI);
    __half* Alo = (__half*)(smem + SM_ALO);
    #pragma unroll 4
    for (int it = 0; it < 16; it++) {
        int idx = it * 256 + tid;        // float4 slot, 4096 total
        int row = idx >> 5;
        int k4 = (idx & 31) * 4;
        int grow = r0 + row;
        float4 v = make_float4(0.f, 0.f, 0.f, 0.f);
        if (grow < N_NODES) v = *(const float4*)&x[(size_t)grow * F_IN + k4];

        float fv[4] = {v.x, v.y, v.z, v.w};
        __half h[4], l[4];
        #pragma unroll
        for (int j = 0; j < 4; j++) {
            h[j] = __float2half_rn(fv[j]);
            l[j] = __float2half_rn(fv[j] - __half2float(h[j]));
        }
        int base = row * AP + k4;
        *(__half2*)&Ahi[base]     = __half2(h[0], h[1]);
        *(__half2*)&Ahi[base + 2] = __half2(h[2], h[3]);
        *(__half2*)&Alo[base]     = __half2(l[0], l[1]);
        *(__half2*)&Alo[base + 2] = __half2(l[2], l[3]);
    }

    // ---- B: B[n][k] = fp16(W[k][n] * inv_sigma); thread: k=tid>>1, half n range
    __half* B = (__half*)(smem + SM_B);
    {
        int k = tid >> 1;
        int n4base = (tid & 1) * 8;
        const float4* wr = (const float4*)(W + (size_t)k * F_OUT);
        #pragma unroll
        for (int n4i = 0; n4i < 8; n4i++) {
            int n4 = n4base + n4i;
            float4 wv = wr[n4];
            B[(n4 * 4 + 0) * AP + k] = __float2half_rn(wv.x * inv_sigma);
            B[(n4 * 4 + 1) * AP + k] = __float2half_rn(wv.y * inv_sigma);
            B[(n4 * 4 + 2) * AP + k] = __float2half_rn(wv.z * inv_sigma);
            B[(n4 * 4 + 3) * AP + k] = __float2half_rn(wv.w * inv_sigma);
        }
    }
    __syncthreads();

    // ---- fragment mainloop: each warp 32 rows (2 m16) x 32 cols (4 n8)
    float acc[2][4][4];
    #pragma unroll
    for (int mt = 0; mt < 2; mt++)
        #pragma unroll
        for (int nt = 0; nt < 4; nt++)
            #pragma unroll
            for (int j = 0; j < 4; j++) acc[mt][nt][j] = 0.f;

    int lm = lane & 15;
    int lk = (lane >> 4) * 8;
    int bn = lane & 7;
    int bk = ((lane >> 3) & 1) * 8;

    uint32_t aH0 = sb + SM_AHI + (uint32_t)(mwid * 32 + lm) * AP * 2;
    uint32_t aH1 = aH0 + 16u * AP * 2;
    uint32_t aL0 = sb + SM_ALO + (uint32_t)(mwid * 32 + lm) * AP * 2;
    uint32_t aL1 = aL0 + 16u * AP * 2;
    uint32_t bB  = sb + SM_B + (uint32_t)(nwid * 32 + bn) * AP * 2;

    #pragma unroll
    for (int ks = 0; ks < 8; ks++) {
        int kb = ks * 16;
        uint32_t aoff = (uint32_t)(kb + lk) * 2;
        uint32_t boff = (uint32_t)(kb + bk) * 2;

        uint32_t ah0[4], ah1[4], al0[4], al1[4];
        LDSM_X4(ah0, aH0 + aoff);
        LDSM_X4(ah1, aH1 + aoff);
        LDSM_X4(al0, aL0 + aoff);
        LDSM_X4(al1, aL1 + aoff);

        #pragma unroll
        for (int nt = 0; nt < 4; nt++) {
            uint32_t bh[2];
            uint32_t nstep = (uint32_t)(nt * 8) * AP * 2;
            LDSM_X2(bh, bB + nstep + boff);
            MMA_F16(acc[0][nt], ah0, bh);
            MMA_F16(acc[0][nt], al0, bh);
            MMA_F16(acc[1][nt], ah1, bh);
            MMA_F16(acc[1][nt], al1, bh);
        }
    }

    // ---- epilogue: read deg first (both n-warps), sync, then write + reset
    int rr[2][2];
    float idv[2][2];
    #pragma unroll
    for (int mt = 0; mt < 2; mt++) {
        int r1 = r0 + mwid * 32 + mt * 16 + (lane >> 2);
        int r2 = r1 + 8;
        rr[mt][0] = r1; rr[mt][1] = r2;
        idv[mt][0] = (r1 < N_NODES) ? 1.0f / (s_deg[r1] + 1.0f) : 0.f;
        idv[mt][1] = (r2 < N_NODES) ? 1.0f / (s_deg[r2] + 1.0f) : 0.f;
    }
    __syncthreads();   // all deg reads complete before any reset

    #pragma unroll
    for (int mt = 0; mt < 2; mt++) {
        #pragma unroll
        for (int h = 0; h < 2; h++) {
            int r = rr[mt][h];
            if (r >= N_NODES) continue;
            float id = idv[mt][h];
            if (nwid == 0 && (lane & 3) == 0) {
                s_dis[r] = sqrtf(id);
                s_deg[r] = 0.0f;
            }
            #pragma unroll
            for (int nt = 0; nt < 4; nt++) {
                int n0 = nwid * 32 + nt * 8 + (lane & 3) * 2;
                float2 bv = *(const float2*)&bias[n0];
                float2 xp = make_float2(acc[mt][nt][h * 2], acc[mt][nt][h * 2 + 1]);
                *(__half2*)&s_xph[(size_t)r * F_OUT + n0] = __floats2half2_rn(xp.x, xp.y);
                *(float2*)&out[(size_t)r * F_OUT + n0] =
                    make_float2(xp.x * id + bv.x, xp.y * id + bv.y);
            }
        }
    }
}

// ---------------------------------------------------------------------------
// Edge aggregation: out[col] += dis[row]*sigmoid(ew)*dis[col] * xp_fp16[row]
// 4 edges per warp: 16 lanes/edge, 2 edges per lane group (MLP=2 gathers).
// Gather is fp16 (128B/edge = 1 line); scatter stays float4 fp32 RED.
// ---------------------------------------------------------------------------
__global__ __launch_bounds__(256) void k_edge(const int* __restrict__ ei,
                                              const float* __restrict__ ew,
                                              float* __restrict__ out) {
    int gtid = blockIdx.x * blockDim.x + threadIdx.x;
    int lane = threadIdx.x & 31;
    int half = lane >> 4;
    int sub  = lane & 15;
    int ebase = (gtid >> 5) * 4 + half * 2;

    int   rowv[2], colv[2];
    float cf[2];
    #pragma unroll
    for (int j = 0; j < 2; j++) {
        int e = ebase + j;
        rowv[j] = ei[e];
        colv[j] = ei[N_EDGES + e];
        float w = 1.f / (1.f + __expf(-ew[e]));
        cf[j] = s_dis[rowv[j]] * w * s_dis[colv[j]];
    }

    uint2 g0 = *(const uint2*)&s_xph[(size_t)rowv[0] * F_OUT + sub * 4];
    uint2 g1 = *(const uint2*)&s_xph[(size_t)rowv[1] * F_OUT + sub * 4];

    float2 a0 = __half22float2(*(__half2*)&g0.x);
    float2 a1 = __half22float2(*(__half2*)&g0.y);
    float4 m0 = make_float4(a0.x * cf[0], a0.y * cf[0], a1.x * cf[0], a1.y * cf[0]);
    atomicAdd((float4*)&out[(size_t)colv[0] * F_OUT + sub * 4], m0);

    float2 b0 = __half22float2(*(__half2*)&g1.x);
    float2 b1 = __half22float2(*(__half2*)&g1.y);
    float4 m1 = make_float4(b0.x * cf[1], b0.y * cf[1], b1.x * cf[1], b1.y * cf[1]);
    atomicAdd((float4*)&out[(size_t)colv[1] * F_OUT + sub * 4], m1);
}

// ---------------------------------------------------------------------------
extern "C" void kernel_launch(void* const* d_in, const int* in_sizes, int n_in,
                              void* d_out, int out_size) {
    const float* x    = (const float*)d_in[0];
    const int*   ei   = (const int*)d_in[1];
    const float* W    = (const float*)d_in[2];
    const float* bias = (const float*)d_in[3];
    const float* ew   = (const float*)d_in[4];
    const float* u    = (const float*)d_in[5];
    float* out = (float*)d_out;

    cudaFuncSetAttribute(k_gemm, cudaFuncAttributeMaxDynamicSharedMemorySize, SM_TOTAL);

    // block 0 = sigma (overlaps), blocks 1..586 = deg
    int deg_blocks = (N_EDGES / 4 + 255) / 256;
    k_deg_sigma<<<deg_blocks + 1, 256>>>(ei, ew, W, u);
    k_gemm<<<(N_NODES + TM - 1) / TM, 256, SM_TOTAL>>>(x, W, bias, out);
    // 4 edges per warp: 600000/4 = 150000 warps / 8 per block = 18750 blocks
    k_edge<<<18750, 256>>>(ei, ew, out);
}